// round 3
// baseline (speedup 1.0000x reference)
#include <cuda_runtime.h>

#define Bv 4
#define Cv 256
#define Hv 64
#define Wv 64
#define HWv 4096

// Scratch (static device globals — no allocation in kernel_launch)
__device__ float g_Q[Bv * Cv * HWv];      // 16 MB
__device__ float g_K[Bv * Cv * HWv];      // 16 MB
__device__ float g_V[Bv * Cv * HWv];      // 16 MB
__device__ float g_qmask[Cv * Wv];        // 16384: column max of Q viewed [256,16384]
__device__ float g_mval[Bv * HWv];        // 16384: max over n of soft[b,n,m]
__device__ float g_m2[Bv * Hv];           // 256

// ---------- packed f32x2 helpers ----------
__device__ __forceinline__ float2 pk2(float x, float y) {
    float2 r;
    asm("mov.b64 %0, {%1, %2};" : "=l"(*(unsigned long long*)&r) : "f"(x), "f"(y));
    return r;
}
__device__ __forceinline__ void fma2(float2& d, float2 a, float2 b) {
    asm("fma.rn.f32x2 %0, %1, %2, %0;"
        : "+l"(*(unsigned long long*)&d)
        : "l"(*(unsigned long long*)&a), "l"(*(unsigned long long*)&b));
}

// ---------- Kernel A: conv1x1 GEMMs -> Q, K, V ----------
// out[b, o, n] = sum_c W[o,c] * X[b,c,n] + bias[o]
// grid: (HW/64, C/64, 12)   z: wsel = z>>2 in {Q,K,V}, b = z&3
__global__ __launch_bounds__(256) void qkv_kernel(
    const float* __restrict__ X,
    const float* __restrict__ Wq, const float* __restrict__ bq,
    const float* __restrict__ Wk, const float* __restrict__ bk,
    const float* __restrict__ Wvv, const float* __restrict__ bvv)
{
    __shared__ float Ws[16][64];
    __shared__ float Xs[16][64];

    int z = blockIdx.z;
    int wsel = z >> 2, b = z & 3;
    const float* W    = (wsel == 0) ? Wq : (wsel == 1) ? Wk : Wvv;
    const float* bias = (wsel == 0) ? bq : (wsel == 1) ? bk : bvv;
    float* out        = (wsel == 0) ? g_Q : (wsel == 1) ? g_K : g_V;

    int n0 = blockIdx.x * 64, o0 = blockIdx.y * 64;
    int tx = threadIdx.x, ty = threadIdx.y;
    int tid = ty * 16 + tx;

    float2 acc[4][2];
#pragma unroll
    for (int i = 0; i < 4; i++) { acc[i][0] = pk2(0.f, 0.f); acc[i][1] = pk2(0.f, 0.f); }

    for (int c0 = 0; c0 < Cv; c0 += 16) {
        {   // W tile: Ws[c][o], 64 o x 16 c
            int o_l = tid >> 2, c_l = (tid & 3) * 4;
            float4 w4 = *(const float4*)&W[(o0 + o_l) * Cv + c0 + c_l];
            Ws[c_l + 0][o_l] = w4.x;
            Ws[c_l + 1][o_l] = w4.y;
            Ws[c_l + 2][o_l] = w4.z;
            Ws[c_l + 3][o_l] = w4.w;
        }
        {   // X tile: Xs[c][n]
            int kkl = tid >> 4, nl = (tid & 15) * 4;
            *(float4*)&Xs[kkl][nl] =
                *(const float4*)&X[(b * Cv + c0 + kkl) * HWv + n0 + nl];
        }
        __syncthreads();
#pragma unroll
        for (int k = 0; k < 16; k++) {
            float4 w4  = *(const float4*)&Ws[k][ty * 4];
            float2 x01 = *(const float2*)&Xs[k][tx * 4];
            float2 x23 = *(const float2*)&Xs[k][tx * 4 + 2];
            float2 ww;
            ww = pk2(w4.x, w4.x); fma2(acc[0][0], ww, x01); fma2(acc[0][1], ww, x23);
            ww = pk2(w4.y, w4.y); fma2(acc[1][0], ww, x01); fma2(acc[1][1], ww, x23);
            ww = pk2(w4.z, w4.z); fma2(acc[2][0], ww, x01); fma2(acc[2][1], ww, x23);
            ww = pk2(w4.w, w4.w); fma2(acc[3][0], ww, x01); fma2(acc[3][1], ww, x23);
        }
        __syncthreads();
    }
#pragma unroll
    for (int i = 0; i < 4; i++) {
        float bb = bias[o0 + ty * 4 + i];
        float4 r;
        r.x = acc[i][0].x + bb; r.y = acc[i][0].y + bb;
        r.z = acc[i][1].x + bb; r.w = acc[i][1].y + bb;
        *(float4*)&out[(b * Cv + o0 + ty * 4 + i) * HWv + n0 + tx * 4] = r;
    }
}

// ---------- Kernel B: Q_mask (column max of Q flat [256, 16384]) + init g_mval ----------
__global__ void qmask_kernel()
{
    int j = blockIdx.x * 256 + threadIdx.x;   // 0..16383
    float m = -3.4e38f;
    for (int r = 0; r < 256; r++)
        m = fmaxf(m, g_Q[r * 16384 + j]);
    g_qmask[j] = m;
    g_mval[j] = 0.f;   // same size, init for atomicMax
}

// ---------- Kernel C: scores + batch-softmax + max over queries ----------
// Block computes a 64(n) x 64(m) tile of scores for ALL 4 batches,
// softmaxes over batch per cell, reduces max over n, atomicMax into g_mval[b][m].
__global__ __launch_bounds__(256) void scores_kernel()
{
    __shared__ float Qs[4][16][64];
    __shared__ float Ks[4][16][64];

    int tx = threadIdx.x, ty = threadIdx.y;
    int tid = ty * 16 + tx;
    int n0 = blockIdx.x * 64, m0 = blockIdx.y * 64;

    float2 acc[4][4][2];   // [batch][i_n][j_m pair]
#pragma unroll
    for (int b = 0; b < 4; b++)
#pragma unroll
        for (int i = 0; i < 4; i++) { acc[b][i][0] = pk2(0.f, 0.f); acc[b][i][1] = pk2(0.f, 0.f); }

    int kkl = tid >> 4, cl4 = (tid & 15) * 4;
    for (int c0 = 0; c0 < Cv; c0 += 16) {
#pragma unroll
        for (int b = 0; b < 4; b++) {
            *(float4*)&Qs[b][kkl][cl4] =
                *(const float4*)&g_Q[(b * Cv + c0 + kkl) * HWv + n0 + cl4];
            *(float4*)&Ks[b][kkl][cl4] =
                *(const float4*)&g_K[(b * Cv + c0 + kkl) * HWv + m0 + cl4];
        }
        __syncthreads();
#pragma unroll
        for (int k = 0; k < 16; k++) {
#pragma unroll
            for (int b = 0; b < 4; b++) {
                float4 q4  = *(const float4*)&Qs[b][k][ty * 4];
                float2 k01 = *(const float2*)&Ks[b][k][tx * 4];
                float2 k23 = *(const float2*)&Ks[b][k][tx * 4 + 2];
                float2 qq;
                qq = pk2(q4.x, q4.x); fma2(acc[b][0][0], qq, k01); fma2(acc[b][0][1], qq, k23);
                qq = pk2(q4.y, q4.y); fma2(acc[b][1][0], qq, k01); fma2(acc[b][1][1], qq, k23);
                qq = pk2(q4.z, q4.z); fma2(acc[b][2][0], qq, k01); fma2(acc[b][2][1], qq, k23);
                qq = pk2(q4.w, q4.w); fma2(acc[b][3][0], qq, k01); fma2(acc[b][3][1], qq, k23);
            }
        }
        __syncthreads();
    }

    // Softmax over batch per cell, track per-(b, j) max over this thread's 4 n rows.
    const float scl = 0.0625f;   // 1/sqrt(256)
    float colmax[4][4];
#pragma unroll
    for (int b = 0; b < 4; b++)
#pragma unroll
        for (int j = 0; j < 4; j++) colmax[b][j] = 0.f;

#pragma unroll
    for (int i = 0; i < 4; i++) {
#pragma unroll
        for (int jp = 0; jp < 2; jp++) {
#pragma unroll
            for (int lane = 0; lane < 2; lane++) {
                float s[4];
#pragma unroll
                for (int b = 0; b < 4; b++)
                    s[b] = (lane == 0 ? acc[b][i][jp].x : acc[b][i][jp].y) * scl;
                float mx = fmaxf(fmaxf(s[0], s[1]), fmaxf(s[2], s[3]));
                float e[4];
                float sum = 0.f;
#pragma unroll
                for (int b = 0; b < 4; b++) { e[b] = __expf(s[b] - mx); sum += e[b]; }
                float inv = 1.f / sum;
                int j = jp * 2 + lane;
#pragma unroll
                for (int b = 0; b < 4; b++)
                    colmax[b][j] = fmaxf(colmax[b][j], e[b] * inv);
            }
        }
    }

    // Reduce over ty (n direction) via shared (reuse Qs), then atomicMax to global.
    float* red = &Qs[0][0][0];   // 4096 floats, safe after trailing __syncthreads
#pragma unroll
    for (int b = 0; b < 4; b++)
#pragma unroll
        for (int j = 0; j < 4; j++)
            red[ty * 256 + tx * 16 + b * 4 + j] = colmax[b][j];
    __syncthreads();
    for (int s = 8; s > 0; s >>= 1) {
        if (ty < s) {
#pragma unroll
            for (int q = 0; q < 16; q++) {
                int col = tx * 16 + q;
                red[ty * 256 + col] = fmaxf(red[ty * 256 + col], red[(ty + s) * 256 + col]);
            }
        }
        __syncthreads();
    }
    {   // one atomic per column: col = txd*16 + b*4 + j
        int col = tid;
        int txd = col >> 4, b = (col >> 2) & 3, j = col & 3;
        int m = m0 + txd * 4 + j;
        atomicMax((int*)&g_mval[b * HWv + m], __float_as_int(red[col]));
    }
}

// ---------- Kernel D: m2[r] = max over 64 of g_mval viewed [256, 64] ----------
__global__ void m2_kernel()
{
    int r = threadIdx.x;   // 256 threads, 1 block
    float m = 0.f;
    for (int w = 0; w < 64; w++)
        m = fmaxf(m, g_mval[r * 64 + w]);
    g_m2[r] = m;
}

// ---------- Kernel E: out = V * (1 + m2[b*64 + c/4] * qmask[(c%4)*4096 + n]) ----------
__global__ __launch_bounds__(256) void out_kernel(float* __restrict__ out)
{
    int t = blockIdx.x * 256 + threadIdx.x;   // over 1,048,576 float4 groups
    int n4 = t & 1023;
    int c  = (t >> 10) & 255;
    int b  = t >> 18;
    float a = g_m2[b * 64 + (c >> 2)];
    float4 qm = *(const float4*)&g_qmask[((c & 3) << 12) + n4 * 4];
    float4 v  = *(const float4*)&g_V[((b << 8) + c) * HWv + n4 * 4];
    float4 r;
    r.x = v.x + v.x * a * qm.x;
    r.y = v.y + v.y * a * qm.y;
    r.z = v.z + v.z * a * qm.z;
    r.w = v.w + v.w * a * qm.w;
    ((float4*)out)[t] = r;
}

extern "C" void kernel_launch(void* const* d_in, const int* in_sizes, int n_in,
                              void* d_out, int out_size)
{
    const float* fuse = (const float*)d_in[0];
    const float* Wq   = (const float*)d_in[1];
    const float* bq   = (const float*)d_in[2];
    const float* Wk   = (const float*)d_in[3];
    const float* bk   = (const float*)d_in[4];
    const float* Wvv  = (const float*)d_in[5];
    const float* bvv  = (const float*)d_in[6];
    float* out = (float*)d_out;

    dim3 blk(16, 16);
    qkv_kernel<<<dim3(HWv / 64, Cv / 64, 12), blk>>>(fuse, Wq, bq, Wk, bk, Wvv, bvv);
    qmask_kernel<<<64, 256>>>();
    scores_kernel<<<dim3(HWv / 64, HWv / 64), blk>>>();
    m2_kernel<<<1, 256>>>();
    out_kernel<<<4096, 256>>>(out);
}

// round 6
// speedup vs baseline: 2.8855x; 2.8855x over previous
#include <cuda_runtime.h>
#include <cuda_fp16.h>
#include <cstdint>

#define Bv 4
#define Cv 256
#define Hv 64
#define Wv 64
#define HWv 4096

// ---------------- global scratch ----------------
__device__ float  g_Q [Bv * Cv * HWv];     // fp32 [b][c][n]  (for qmask)
__device__ float  g_V [Bv * Cv * HWv];     // fp32 [b][c][n]
__device__ __half g_Qh[Bv * HWv * Cv];     // fp16 [b][n][c]  (MMA A)
__device__ __half g_Kh[Bv * HWv * Cv];     // fp16 [b][m][c]  (MMA B)
__device__ float  g_qmask[Cv * Wv];        // 16384
__device__ float  g_mval [Bv * HWv];       // 16384
__device__ float  g_m2   [Bv * Hv];        // 256

// ---------------- f32x2 helpers ----------------
__device__ __forceinline__ float2 pk2(float x, float y) {
    float2 r;
    asm("mov.b64 %0, {%1, %2};" : "=l"(*(unsigned long long*)&r) : "f"(x), "f"(y));
    return r;
}
__device__ __forceinline__ void fma2(float2& d, float2 a, float2 b) {
    asm("fma.rn.f32x2 %0, %1, %2, %0;"
        : "+l"(*(unsigned long long*)&d)
        : "l"(*(unsigned long long*)&a), "l"(*(unsigned long long*)&b));
}

__device__ __forceinline__ uint32_t smem_u32(const void* p) {
    uint32_t a;
    asm("{ .reg .u64 t; cvta.to.shared.u64 t, %1; cvt.u32.u64 %0, t; }" : "=r"(a) : "l"(p));
    return a;
}
__device__ __forceinline__ void ldsm4(uint32_t* r, uint32_t addr) {
    asm volatile("ldmatrix.sync.aligned.m8n8.x4.shared.b16 {%0,%1,%2,%3}, [%4];"
                 : "=r"(r[0]), "=r"(r[1]), "=r"(r[2]), "=r"(r[3]) : "r"(addr));
}
__device__ __forceinline__ void mma16816(float* d, const uint32_t* a, const uint32_t* b) {
    asm volatile(
        "mma.sync.aligned.m16n8k16.row.col.f32.f16.f16.f32 "
        "{%0,%1,%2,%3}, {%4,%5,%6,%7}, {%8,%9}, {%0,%1,%2,%3};"
        : "+f"(d[0]), "+f"(d[1]), "+f"(d[2]), "+f"(d[3])
        : "r"(a[0]), "r"(a[1]), "r"(a[2]), "r"(a[3]), "r"(b[0]), "r"(b[1]));
}

// ---------------- Kernel A: conv1x1 -> Q(fp32+fp16T), K(fp16T), V(fp32) ----------------
__global__ __launch_bounds__(256) void qkv_kernel(
    const float* __restrict__ X,
    const float* __restrict__ Wq, const float* __restrict__ bq,
    const float* __restrict__ Wk, const float* __restrict__ bk,
    const float* __restrict__ Wvv, const float* __restrict__ bvv)
{
    __shared__ float Ws[16][64];
    __shared__ float Xs[16][64];
    __shared__ __half Tr[64][80];   // transposed staging, stride 160B (16B-aligned rows)

    int z = blockIdx.z;
    int wsel = z >> 2, b = z & 3;
    const float* W    = (wsel == 0) ? Wq : (wsel == 1) ? Wk : Wvv;
    const float* bias = (wsel == 0) ? bq : (wsel == 1) ? bk : bvv;

    int n0 = blockIdx.x * 64, o0 = blockIdx.y * 64;
    int tx = threadIdx.x, ty = threadIdx.y;
    int tid = ty * 16 + tx;

    float2 acc[4][2];
#pragma unroll
    for (int i = 0; i < 4; i++) { acc[i][0] = pk2(0.f, 0.f); acc[i][1] = pk2(0.f, 0.f); }

    for (int c0 = 0; c0 < Cv; c0 += 16) {
        {
            int o_l = tid >> 2, c_l = (tid & 3) * 4;
            float4 w4 = *(const float4*)&W[(o0 + o_l) * Cv + c0 + c_l];
            Ws[c_l + 0][o_l] = w4.x;
            Ws[c_l + 1][o_l] = w4.y;
            Ws[c_l + 2][o_l] = w4.z;
            Ws[c_l + 3][o_l] = w4.w;
        }
        {
            int kkl = tid >> 4, nl = (tid & 15) * 4;
            *(float4*)&Xs[kkl][nl] =
                *(const float4*)&X[(b * Cv + c0 + kkl) * HWv + n0 + nl];
        }
        __syncthreads();
#pragma unroll
        for (int k = 0; k < 16; k++) {
            float4 w4  = *(const float4*)&Ws[k][ty * 4];
            float2 x01 = *(const float2*)&Xs[k][tx * 4];
            float2 x23 = *(const float2*)&Xs[k][tx * 4 + 2];
            float2 ww;
            ww = pk2(w4.x, w4.x); fma2(acc[0][0], ww, x01); fma2(acc[0][1], ww, x23);
            ww = pk2(w4.y, w4.y); fma2(acc[1][0], ww, x01); fma2(acc[1][1], ww, x23);
            ww = pk2(w4.z, w4.z); fma2(acc[2][0], ww, x01); fma2(acc[2][1], ww, x23);
            ww = pk2(w4.w, w4.w); fma2(acc[3][0], ww, x01); fma2(acc[3][1], ww, x23);
        }
        __syncthreads();
    }

    if (wsel != 1) {   // fp32 Q / V
        float* out = (wsel == 0) ? g_Q : g_V;
#pragma unroll
        for (int i = 0; i < 4; i++) {
            float bb = bias[o0 + ty * 4 + i];
            float4 r;
            r.x = acc[i][0].x + bb; r.y = acc[i][0].y + bb;
            r.z = acc[i][1].x + bb; r.w = acc[i][1].y + bb;
            *(float4*)&out[(b * Cv + o0 + ty * 4 + i) * HWv + n0 + tx * 4] = r;
        }
    }
    if (wsel < 2) {    // fp16 transposed Q / K
        __half* outh = (wsel == 0) ? g_Qh : g_Kh;
#pragma unroll
        for (int i = 0; i < 4; i++) {
            float bb = bias[o0 + ty * 4 + i];
            Tr[tx * 4 + 0][ty * 4 + i] = __float2half(acc[i][0].x + bb);
            Tr[tx * 4 + 1][ty * 4 + i] = __float2half(acc[i][0].y + bb);
            Tr[tx * 4 + 2][ty * 4 + i] = __float2half(acc[i][1].x + bb);
            Tr[tx * 4 + 3][ty * 4 + i] = __float2half(acc[i][1].y + bb);
        }
        __syncthreads();
        int row = tid >> 2, q = tid & 3;
        const uint4* src = (const uint4*)&Tr[row][q * 16];
        uint4* dst = (uint4*)&outh[((size_t)b * HWv + n0 + row) * Cv + o0 + q * 16];
        dst[0] = src[0];
        dst[1] = src[1];
    }
}

// ---------------- Kernel B: Q_mask + init g_mval ----------------
__global__ void qmask_kernel()
{
    int j = blockIdx.x * 256 + threadIdx.x;
    float m = -3.4e38f;
    for (int r = 0; r < 256; r++)
        m = fmaxf(m, g_Q[r * 16384 + j]);
    g_qmask[j] = m;
    g_mval[j] = 0.f;
}

// ---------------- Kernel C: HMMA scores + batch softmax + n-max ----------------
// CTA: 64(n) x 64(m) x 4 batches. 8 warps: wn = wid>>2 (2), wm = wid&3 (4).
// Warp tile: 32n x 16m -> 2x2 m16n8k16 fragments, 4 batches accumulated.
#define SMQ 0
#define SMK 32768
#define SMR 65536
#define SMTOT (65536 + 2048)

__global__ __launch_bounds__(256) void scores_hmma_kernel()
{
    extern __shared__ __align__(128) char dsm[];
    uint32_t sb = smem_u32(dsm);
    float* red = (float*)(dsm + SMR);   // [2 wn][4 b][64 m]

    int tid = threadIdx.x;
    int wid = tid >> 5, lid = tid & 31;
    int wn = wid >> 2, wm = wid & 3;
    int n0 = blockIdx.x * 64, m0 = blockIdx.y * 64;

    float acc[4][2][2][4];
#pragma unroll
    for (int b = 0; b < 4; b++)
#pragma unroll
        for (int i = 0; i < 2; i++)
#pragma unroll
            for (int j = 0; j < 2; j++)
#pragma unroll
                for (int r = 0; r < 4; r++) acc[b][i][j][r] = 0.f;

    // ldmatrix source addresses (within swizzled tile), fixed per thread
    int arow = wn * 32 + (lid & 15);
    int acolh = (lid >> 4) * 8;                          // +k within step
    int brow = wm * 16 + (lid & 7) + ((lid >> 4) << 3);
    int bcolh = ((lid >> 3) & 1) * 8;

    for (int b = 0; b < 4; b++) {
        __syncthreads();   // protect SMEM reuse across batches
        const __half* Qp = g_Qh + ((size_t)b * HWv + n0) * Cv;
        const __half* Kp = g_Kh + ((size_t)b * HWv + m0) * Cv;
#pragma unroll
        for (int it = 0; it < 8; it++) {   // 64 rows x 256 cols fp16, both tiles
            int idx = it * 256 + tid;
            int r = idx >> 5, c8 = (idx & 31) * 8;
            uint32_t off = (uint32_t)(((c8 >> 6) * 64 + r) * 128 + (c8 & 63) * 2);
            off ^= (off >> 3) & 0x70;
            *(uint4*)(dsm + SMQ + off) = *(const uint4*)(Qp + r * Cv + c8);
            *(uint4*)(dsm + SMK + off) = *(const uint4*)(Kp + r * Cv + c8);
        }
        __syncthreads();

#pragma unroll 4
        for (int ks = 0; ks < 16; ks++) {
            uint32_t a[2][4], bb[4];
            {
                int c = ks * 16 + bcolh;
                uint32_t off = (uint32_t)(((c >> 6) * 64 + brow) * 128 + (c & 63) * 2);
                off ^= (off >> 3) & 0x70;
                ldsm4(bb, sb + SMK + off);
            }
#pragma unroll
            for (int in = 0; in < 2; in++) {
                int r = arow + in * 16;
                int c = ks * 16 + acolh;
                uint32_t off = (uint32_t)(((c >> 6) * 64 + r) * 128 + (c & 63) * 2);
                off ^= (off >> 3) & 0x70;
                ldsm4(a[in], sb + SMQ + off);
            }
#pragma unroll
            for (int in = 0; in < 2; in++) {
                mma16816(acc[b][in][0], a[in], bb);
                mma16816(acc[b][in][1], a[in], bb + 2);
            }
        }
    }

    // ---- epilogue: batch softmax per cell, max over n ----
    const float scl = 0.0625f;
    float cm[4][2][2];   // [b][jm][col parity]
#pragma unroll
    for (int b = 0; b < 4; b++)
#pragma unroll
        for (int j = 0; j < 2; j++) { cm[b][j][0] = 0.f; cm[b][j][1] = 0.f; }

#pragma unroll
    for (int in = 0; in < 2; in++)
#pragma unroll
        for (int jm = 0; jm < 2; jm++)
#pragma unroll
            for (int r = 0; r < 4; r++) {
                float s0 = acc[0][in][jm][r] * scl;
                float s1 = acc[1][in][jm][r] * scl;
                float s2 = acc[2][in][jm][r] * scl;
                float s3 = acc[3][in][jm][r] * scl;
                float mx = fmaxf(fmaxf(s0, s1), fmaxf(s2, s3));
                float e0 = __expf(s0 - mx), e1 = __expf(s1 - mx);
                float e2 = __expf(s2 - mx), e3 = __expf(s3 - mx);
                float inv = 1.f / (e0 + e1 + e2 + e3);
                int p = r & 1;
                cm[0][jm][p] = fmaxf(cm[0][jm][p], e0 * inv);
                cm[1][jm][p] = fmaxf(cm[1][jm][p], e1 * inv);
                cm[2][jm][p] = fmaxf(cm[2][jm][p], e2 * inv);
                cm[3][jm][p] = fmaxf(cm[3][jm][p], e3 * inv);
            }

    // reduce over row-group lanes (bits 2..4 of lane id)
#pragma unroll
    for (int s = 4; s <= 16; s <<= 1)
#pragma unroll
        for (int b = 0; b < 4; b++)
#pragma unroll
            for (int j = 0; j < 2; j++) {
                cm[b][j][0] = fmaxf(cm[b][j][0], __shfl_xor_sync(0xffffffffu, cm[b][j][0], s));
                cm[b][j][1] = fmaxf(cm[b][j][1], __shfl_xor_sync(0xffffffffu, cm[b][j][1], s));
            }

    if (lid < 4) {
#pragma unroll
        for (int b = 0; b < 4; b++)
#pragma unroll
            for (int j = 0; j < 2; j++)
#pragma unroll
                for (int p = 0; p < 2; p++) {
                    int cl = wm * 16 + j * 8 + lid * 2 + p;
                    red[(wn * 4 + b) * 64 + cl] = cm[b][j][p];
                }
    }
    __syncthreads();
    {
        int b = tid >> 6, c = tid & 63;
        float v = fmaxf(red[b * 64 + c], red[(4 + b) * 64 + c]);
        atomicMax((int*)&g_mval[b * HWv + m0 + c], __float_as_int(v));
    }
}

// ---------------- Kernel D: m2 ----------------
__global__ void m2_kernel()
{
    int r = blockIdx.x, t = threadIdx.x;   // 256 blocks x 32 threads
    float v = fmaxf(g_mval[r * 64 + t], g_mval[r * 64 + 32 + t]);
#pragma unroll
    for (int s = 16; s > 0; s >>= 1)
        v = fmaxf(v, __shfl_xor_sync(0xffffffffu, v, s));
    if (t == 0) g_m2[r] = v;
}

// ---------------- Kernel E: output ----------------
__global__ __launch_bounds__(256) void out_kernel(float* __restrict__ out)
{
    int t = blockIdx.x * 256 + threadIdx.x;
    int n4 = t & 1023;
    int c  = (t >> 10) & 255;
    int b  = t >> 18;
    float a = g_m2[b * 64 + (c >> 2)];
    float4 qm = *(const float4*)&g_qmask[((c & 3) << 12) + n4 * 4];
    float4 v  = *(const float4*)&g_V[((b << 8) + c) * HWv + n4 * 4];
    float4 r;
    r.x = v.x + v.x * a * qm.x;
    r.y = v.y + v.y * a * qm.y;
    r.z = v.z + v.z * a * qm.z;
    r.w = v.w + v.w * a * qm.w;
    ((float4*)out)[t] = r;
}

extern "C" void kernel_launch(void* const* d_in, const int* in_sizes, int n_in,
                              void* d_out, int out_size)
{
    const float* fuse = (const float*)d_in[0];
    const float* Wq   = (const float*)d_in[1];
    const float* bq   = (const float*)d_in[2];
    const float* Wk   = (const float*)d_in[3];
    const float* bk   = (const float*)d_in[4];
    const float* Wvv  = (const float*)d_in[5];
    const float* bvv  = (const float*)d_in[6];
    float* out = (float*)d_out;

    cudaFuncSetAttribute(scores_hmma_kernel, cudaFuncAttributeMaxDynamicSharedMemorySize, SMTOT);

    dim3 blk(16, 16);
    qkv_kernel<<<dim3(HWv / 64, Cv / 64, 12), blk>>>(fuse, Wq, bq, Wk, bk, Wvv, bvv);
    qmask_kernel<<<64, 256>>>();
    scores_hmma_kernel<<<dim3(HWv / 64, HWv / 64), 256, SMTOT>>>();
    m2_kernel<<<256, 32>>>();
    out_kernel<<<4096, 256>>>(out);
}